// round 1
// baseline (speedup 1.0000x reference)
#include <cuda_runtime.h>
#include <cuda_bf16.h>

// Entmax15: out = clip(X - tau, 0)^2 with sum(out) = 1 per row,
// X = (masked_scores - rowmax) * 0.5. tau found by Newton on
// f(tau) = sum max(X - tau, 0)^2 - 1 (convex, decreasing; start left of root).

constexpr int S_LEN   = 2048;
constexpr int THREADS = 256;
constexpr float NEG_FILL = -1e4f;

__global__ void __launch_bounds__(THREADS, 6)
entmax15_kernel(const float* __restrict__ scores,
                const int*   __restrict__ mask,
                float*       __restrict__ out)
{
    const long long base = (long long)blockIdx.x * S_LEN;
    const float4* s4 = reinterpret_cast<const float4*>(scores + base);
    const int4*   m4 = reinterpret_cast<const int4*>(mask + base);
    float4*       o4 = reinterpret_cast<float4*>(out + base);

    const int tid  = threadIdx.x;
    const int warp = tid >> 5;
    const int lane = tid & 31;

    // ---- load 8 elems/thread, apply mask ----
    float4 a = s4[tid];
    float4 b = s4[tid + THREADS];
    int4  ma = m4[tid];
    int4  mb = m4[tid + THREADS];

    float x[8];
    x[0] = ma.x ? a.x : NEG_FILL;
    x[1] = ma.y ? a.y : NEG_FILL;
    x[2] = ma.z ? a.z : NEG_FILL;
    x[3] = ma.w ? a.w : NEG_FILL;
    x[4] = mb.x ? b.x : NEG_FILL;
    x[5] = mb.y ? b.y : NEG_FILL;
    x[6] = mb.z ? b.z : NEG_FILL;
    x[7] = mb.w ? b.w : NEG_FILL;

    __shared__ float shA[8];
    __shared__ float shB[8];
    __shared__ float sh_bcast[2];

    // ---- block max ----
    float mx = x[0];
    #pragma unroll
    for (int i = 1; i < 8; ++i) mx = fmaxf(mx, x[i]);
    #pragma unroll
    for (int o = 16; o; o >>= 1) mx = fmaxf(mx, __shfl_xor_sync(0xffffffffu, mx, o));
    if (lane == 0) shA[warp] = mx;
    __syncthreads();
    if (tid == 0) {
        float v = shA[0];
        #pragma unroll
        for (int w = 1; w < 8; ++w) v = fmaxf(v, shA[w]);
        sh_bcast[0] = v;
    }
    __syncthreads();
    mx = sh_bcast[0];

    // ---- alpha=1.5 transform: X = (x - max) * 0.5 ; max(X) == 0 ----
    #pragma unroll
    for (int i = 0; i < 8; ++i) x[i] = (x[i] - mx) * 0.5f;

    // ---- Newton: f(tau) = sum max(X-tau,0)^2 = 1.  tau in [-1, 0). ----
    float tau = -1.0f;
    for (int it = 0; it < 32; ++it) {
        float s1 = 0.0f, s2 = 0.0f;
        #pragma unroll
        for (int i = 0; i < 8; ++i) {
            float d = fmaxf(x[i] - tau, 0.0f);
            s1 += d;
            s2 = fmaf(d, d, s2);
        }
        #pragma unroll
        for (int o = 16; o; o >>= 1) {
            s1 += __shfl_xor_sync(0xffffffffu, s1, o);
            s2 += __shfl_xor_sync(0xffffffffu, s2, o);
        }
        if (lane == 0) { shA[warp] = s1; shB[warp] = s2; }
        __syncthreads();
        if (tid == 0) {
            float t1 = 0.0f, t2 = 0.0f;
            #pragma unroll
            for (int w = 0; w < 8; ++w) { t1 += shA[w]; t2 += shB[w]; }
            float err  = t2 - 1.0f;                      // f(tau) - 1  (>= 0 from left)
            float step = err / fmaxf(2.0f * t1, 1e-20f); // Newton: -f/f'
            sh_bcast[0] = tau + step;
            sh_bcast[1] = (fabsf(err) < 1e-6f || fabsf(step) < 1e-8f) ? 1.0f : 0.0f;
        }
        __syncthreads();
        tau = sh_bcast[0];
        if (sh_bcast[1] != 0.0f) break;
    }

    // ---- emit p = clip(X - tau, 0)^2 ----
    float4 r0, r1;
    float d;
    d = fmaxf(x[0] - tau, 0.0f); r0.x = d * d;
    d = fmaxf(x[1] - tau, 0.0f); r0.y = d * d;
    d = fmaxf(x[2] - tau, 0.0f); r0.z = d * d;
    d = fmaxf(x[3] - tau, 0.0f); r0.w = d * d;
    d = fmaxf(x[4] - tau, 0.0f); r1.x = d * d;
    d = fmaxf(x[5] - tau, 0.0f); r1.y = d * d;
    d = fmaxf(x[6] - tau, 0.0f); r1.z = d * d;
    d = fmaxf(x[7] - tau, 0.0f); r1.w = d * d;
    o4[tid]           = r0;
    o4[tid + THREADS] = r1;
}

extern "C" void kernel_launch(void* const* d_in, const int* in_sizes, int n_in,
                              void* d_out, int out_size)
{
    const float* scores = (const float*)d_in[0];
    const int*   mask   = (const int*)d_in[1];
    float*       out    = (float*)d_out;
    const int rows = in_sizes[0] / S_LEN;
    entmax15_kernel<<<rows, THREADS>>>(scores, mask, out);
}